// round 2
// baseline (speedup 1.0000x reference)
#include <cuda_runtime.h>

#define BATCH  32
#define TSTEPS 1024
#define DIMD   512
#define UNITS  512

// ---------------- barrier state (per batch-group), 128B-separated slots ----
__device__ unsigned int g_cnt[8 * 32];
__device__ unsigned int g_gen[8 * 32];

__device__ __forceinline__ unsigned ld_vol(const unsigned* p) {
    unsigned v;
    asm volatile("ld.volatile.global.u32 %0, [%1];" : "=r"(v) : "l"(p));
    return v;
}

// ---------------- front GEMM: out[M=32768, N=512] = x[M,K=512] @ W[K,N] ----
__global__ __launch_bounds__(256) void gemm_xw(const float* __restrict__ A,
                                               const float* __restrict__ Bm,
                                               float* __restrict__ C) {
    const int K = DIMD, N = UNITS;
    __shared__ float As[16][132];   // [kk][m], padded vs bank conflicts
    __shared__ float Bs[16][128];   // [kk][n]

    const int tid = threadIdx.x;
    const int tx = tid & 15, ty = tid >> 4;
    const int m0 = blockIdx.y * 128;
    const int n0 = blockIdx.x * 128;

    const int ar  = tid >> 2;          // 0..63
    const int ac4 = (tid & 3) * 4;     // 0,4,8,12
    const int br  = tid >> 5;          // 0..7
    const int bj4 = (tid & 31) * 4;    // 0..124

    float acc[8][8];
    #pragma unroll
    for (int i = 0; i < 8; i++)
        #pragma unroll
        for (int j = 0; j < 8; j++) acc[i][j] = 0.f;

    for (int k0 = 0; k0 < K; k0 += 16) {
        #pragma unroll
        for (int h = 0; h < 2; h++) {
            int r = ar + h * 64;
            float4 v = *reinterpret_cast<const float4*>(
                &A[(size_t)(m0 + r) * K + k0 + ac4]);
            As[ac4 + 0][r] = v.x; As[ac4 + 1][r] = v.y;
            As[ac4 + 2][r] = v.z; As[ac4 + 3][r] = v.w;
        }
        #pragma unroll
        for (int h = 0; h < 2; h++) {
            int r = br + h * 8;
            float4 v = *reinterpret_cast<const float4*>(
                &Bm[(size_t)(k0 + r) * N + n0 + bj4]);
            *reinterpret_cast<float4*>(&Bs[r][bj4]) = v;
        }
        __syncthreads();
        #pragma unroll
        for (int kk = 0; kk < 16; kk++) {
            float a[8], b[8];
            #pragma unroll
            for (int i = 0; i < 8; i++) a[i] = As[kk][ty * 8 + i];
            #pragma unroll
            for (int j = 0; j < 8; j++) b[j] = Bs[kk][tx * 8 + j];
            #pragma unroll
            for (int i = 0; i < 8; i++)
                #pragma unroll
                for (int j = 0; j < 8; j++) acc[i][j] += a[i] * b[j];
        }
        __syncthreads();
    }
    #pragma unroll
    for (int i = 0; i < 8; i++) {
        size_t row = (size_t)(m0 + ty * 8 + i) * N + n0 + tx * 8;
        #pragma unroll
        for (int j = 0; j < 8; j += 4) {
            float4 v = make_float4(acc[i][j], acc[i][j + 1], acc[i][j + 2], acc[i][j + 3]);
            *reinterpret_cast<float4*>(&C[row + j]) = v;
        }
    }
}

// ---------------- persistent scan: out[:,t,:] += out[:,t-1,:] @ R ----------
// 128 blocks = 8 batch-groups (4 rows each) x 16 u-groups (32 cols each).
// Barrier only among the 16 blocks of one batch-group (batches independent).
// R kept in registers: lane owns k in {lane+32j} (16 j) x 4 u columns.
__global__ __launch_bounds__(256, 1) void rnn_scan(float* __restrict__ out,
                                                   const float* __restrict__ R) {
    const int bg   = blockIdx.x >> 4;   // 0..7
    const int ug   = blockIdx.x & 15;   // 0..15
    const int b0   = bg * 4;
    const int u0   = ug * 32;
    const int warp = threadIdx.x >> 5;  // 0..7
    const int lane = threadIdx.x & 31;
    const int uw   = u0 + warp * 4;
    const int slot = bg * 32;
    const size_t TU = (size_t)TSTEPS * UNITS;

    // Preload R slice into registers: Rreg[j][c] = R[(lane+32j)][uw+c]
    float Rreg[16][4];
    #pragma unroll
    for (int j = 0; j < 16; j++) {
        float4 v = *reinterpret_cast<const float4*>(
            R + (size_t)(lane + 32 * j) * UNITS + uw);
        Rreg[j][0] = v.x; Rreg[j][1] = v.y; Rreg[j][2] = v.z; Rreg[j][3] = v.w;
    }

    unsigned my_gen = ld_vol(&g_gen[slot]);

    for (int t = 1; t < TSTEPS; t++) {
        const float* h0p = out + (size_t)(b0 + 0) * TU + (size_t)(t - 1) * UNITS;
        const float* h1p = h0p + TU;
        const float* h2p = h1p + TU;
        const float* h3p = h2p + TU;

        float acc[16];
        #pragma unroll
        for (int i = 0; i < 16; i++) acc[i] = 0.f;

        #pragma unroll
        for (int j = 0; j < 16; j++) {
            const int k = lane + 32 * j;
            float h0 = __ldcg(h0p + k);
            float h1 = __ldcg(h1p + k);
            float h2 = __ldcg(h2p + k);
            float h3 = __ldcg(h3p + k);
            #pragma unroll
            for (int c = 0; c < 4; c++) {
                acc[0 + c]  += h0 * Rreg[j][c];
                acc[4 + c]  += h1 * Rreg[j][c];
                acc[8 + c]  += h2 * Rreg[j][c];
                acc[12 + c] += h3 * Rreg[j][c];
            }
        }

        // k-split reduction across the warp
        #pragma unroll
        for (int i = 0; i < 16; i++) {
            #pragma unroll
            for (int off = 16; off >= 1; off >>= 1)
                acc[i] += __shfl_xor_sync(0xffffffffu, acc[i], off);
        }

        if (lane < 16) {
            float s = acc[0];
            #pragma unroll
            for (int i = 1; i < 16; i++) s = (lane == i) ? acc[i] : s;
            const int b = lane >> 2, c = lane & 3;
            float* op = out + (size_t)(b0 + b) * TU + (size_t)t * UNITS + uw + c;
            __stcg(op, __ldcg(op) + s);   // h_t = xw_t + h_{t-1}@R
        }

        // ---- barrier among the 16 blocks of this batch-group ----
        __threadfence();
        __syncthreads();
        if (threadIdx.x == 0) {
            __threadfence();
            if (atomicAdd(&g_cnt[slot], 1u) == 15u) {
                atomicExch(&g_cnt[slot], 0u);
                __threadfence();
                atomicAdd(&g_gen[slot], 1u);
            } else {
                while (ld_vol(&g_gen[slot]) == my_gen) { }
                __threadfence();
            }
        }
        __syncthreads();
        my_gen++;
    }
}

extern "C" void kernel_launch(void* const* d_in, const int* in_sizes, int n_in,
                              void* d_out, int out_size) {
    const float* x = (const float*)d_in[0];   // [32,1024,512]
    const float* W = (const float*)d_in[1];   // [512,512]
    const float* R = (const float*)d_in[2];   // [512,512]
    float* out = (float*)d_out;               // [32,1024,512]

    dim3 grid_gemm(UNITS / 128, (BATCH * TSTEPS) / 128);  // (4, 256)
    gemm_xw<<<grid_gemm, 256>>>(x, W, out);
    rnn_scan<<<128, 256>>>(out, R);
}

// round 3
// speedup vs baseline: 2.4183x; 2.4183x over previous
#include <cuda_runtime.h>

#define BATCH  32
#define TSTEPS 1024
#define DIMD   512
#define UNITS  512
#define UU     512
#define TU     (TSTEPS * UNITS)

// ---------------- scratch (__device__ globals; no allocation) --------------
__device__ float g_RpA[512 * 512];
__device__ float g_RpB[512 * 512];
__device__ float g_carry0[1024 * 512];   // row = chunk*32 + b
__device__ float g_carry1[1024 * 512];
__device__ unsigned int g_cnt[8 * 32];
__device__ unsigned int g_gen[8 * 32];

__device__ __forceinline__ unsigned ld_vol(const unsigned* p) {
    unsigned v;
    asm volatile("ld.volatile.global.u32 %0, [%1];" : "=r"(v) : "l"(p));
    return v;
}

// ---------------- front GEMM: out[32768,512] = x @ W ----------------------
__global__ __launch_bounds__(256) void gemm_xw(const float* __restrict__ A,
                                               const float* __restrict__ Bm,
                                               float* __restrict__ C) {
    const int K = DIMD, N = UNITS;
    __shared__ float As[16][132];
    __shared__ float Bs[16][128];

    const int tid = threadIdx.x;
    const int tx = tid & 15, ty = tid >> 4;
    const int m0 = blockIdx.y * 128;
    const int n0 = blockIdx.x * 128;

    const int ar  = tid >> 2;
    const int ac4 = (tid & 3) * 4;
    const int br  = tid >> 5;
    const int bj4 = (tid & 31) * 4;

    float acc[8][8];
    #pragma unroll
    for (int i = 0; i < 8; i++)
        #pragma unroll
        for (int j = 0; j < 8; j++) acc[i][j] = 0.f;

    for (int k0 = 0; k0 < K; k0 += 16) {
        #pragma unroll
        for (int h = 0; h < 2; h++) {
            int r = ar + h * 64;
            float4 v = *reinterpret_cast<const float4*>(
                &A[(size_t)(m0 + r) * K + k0 + ac4]);
            As[ac4 + 0][r] = v.x; As[ac4 + 1][r] = v.y;
            As[ac4 + 2][r] = v.z; As[ac4 + 3][r] = v.w;
        }
        #pragma unroll
        for (int h = 0; h < 2; h++) {
            int r = br + h * 8;
            float4 v = *reinterpret_cast<const float4*>(
                &Bm[(size_t)(k0 + r) * N + n0 + bj4]);
            *reinterpret_cast<float4*>(&Bs[r][bj4]) = v;
        }
        __syncthreads();
        #pragma unroll
        for (int kk = 0; kk < 16; kk++) {
            float a[8], b[8];
            #pragma unroll
            for (int i = 0; i < 8; i++) a[i] = As[kk][ty * 8 + i];
            #pragma unroll
            for (int j = 0; j < 8; j++) b[j] = Bs[kk][tx * 8 + j];
            #pragma unroll
            for (int i = 0; i < 8; i++)
                #pragma unroll
                for (int j = 0; j < 8; j++) acc[i][j] += a[i] * b[j];
        }
        __syncthreads();
    }
    #pragma unroll
    for (int i = 0; i < 8; i++) {
        size_t row = (size_t)(m0 + ty * 8 + i) * N + n0 + tx * 8;
        #pragma unroll
        for (int j = 0; j < 8; j += 4) {
            float4 v = make_float4(acc[i][j], acc[i][j + 1], acc[i][j + 2], acc[i][j + 3]);
            *reinterpret_cast<float4*>(&C[row + j]) = v;
        }
    }
}

// ---------------- 64x64-tile GEMM over K=512 with row remapping ------------
// MODE 0 (rpow):   C0[gr,:]      = A0[gr,:] @ B               (rows = gridDim.y*64)
// MODE 1 (phase1): out[t(gr,s)] += out[t(gr,s-1)] @ B          (rows = 1024)
// MODE 2 (phase3): C0[gr,:] = A0[gr,:] @ B; if gr>=32: out[t(gr,s)] += C0[gr,:]
// row gr -> batch b = gr&31, chunk = gr>>5, t = chunk*32 + s
template <int MODE>
__global__ __launch_bounds__(256) void gemm64(const float* __restrict__ A0,
                                              const float* __restrict__ B,
                                              float* __restrict__ C0,
                                              float* __restrict__ out,
                                              int s) {
    __shared__ float As[2][16][68];
    __shared__ float Bs[2][16][68];

    const int tid = threadIdx.x;
    const int n0 = blockIdx.x * 64;
    const int r0 = blockIdx.y * 64;

    const int ra = tid >> 2;            // 0..63 (row within tile)
    const int ka = (tid & 3) * 4;       // 0,4,8,12
    const int kb = tid >> 4;            // 0..15
    const int nb = (tid & 15) * 4;      // 0..60
    const int tx = tid & 15, ty = tid >> 4;

    const int grl = r0 + ra;
    const float* arow;
    if (MODE == 1) {
        arow = out + (size_t)(grl & 31) * TU +
               (size_t)((grl >> 5) * 32 + s - 1) * UU;
    } else {
        arow = A0 + (size_t)grl * UU;
    }
    const float* brow = B + (size_t)kb * UU + n0 + nb;

    float4 av = *reinterpret_cast<const float4*>(arow + ka);
    float4 bv = *reinterpret_cast<const float4*>(brow);

    float acc[4][4];
    #pragma unroll
    for (int i = 0; i < 4; i++)
        #pragma unroll
        for (int j = 0; j < 4; j++) acc[i][j] = 0.f;

    for (int kt = 0; kt < 32; kt++) {
        const int bf = kt & 1;
        As[bf][ka + 0][ra] = av.x;
        As[bf][ka + 1][ra] = av.y;
        As[bf][ka + 2][ra] = av.z;
        As[bf][ka + 3][ra] = av.w;
        *reinterpret_cast<float4*>(&Bs[bf][kb][nb]) = bv;
        __syncthreads();
        if (kt < 31) {
            const int k0 = (kt + 1) * 16;
            av = *reinterpret_cast<const float4*>(arow + k0 + ka);
            bv = *reinterpret_cast<const float4*>(brow + (size_t)k0 * UU);
        }
        #pragma unroll
        for (int kk = 0; kk < 16; kk++) {
            float4 a = *reinterpret_cast<const float4*>(&As[bf][kk][ty * 4]);
            float4 b = *reinterpret_cast<const float4*>(&Bs[bf][kk][tx * 4]);
            acc[0][0] += a.x * b.x; acc[0][1] += a.x * b.y;
            acc[0][2] += a.x * b.z; acc[0][3] += a.x * b.w;
            acc[1][0] += a.y * b.x; acc[1][1] += a.y * b.y;
            acc[1][2] += a.y * b.z; acc[1][3] += a.y * b.w;
            acc[2][0] += a.z * b.x; acc[2][1] += a.z * b.y;
            acc[2][2] += a.z * b.z; acc[2][3] += a.z * b.w;
            acc[3][0] += a.w * b.x; acc[3][1] += a.w * b.y;
            acc[3][2] += a.w * b.z; acc[3][3] += a.w * b.w;
        }
    }

    #pragma unroll
    for (int i = 0; i < 4; i++) {
        const int gr = r0 + ty * 4 + i;
        float4 v = make_float4(acc[i][0], acc[i][1], acc[i][2], acc[i][3]);
        if (MODE == 0) {
            *reinterpret_cast<float4*>(C0 + (size_t)gr * UU + n0 + tx * 4) = v;
        } else if (MODE == 1) {
            float* p = out + (size_t)(gr & 31) * TU +
                       (size_t)((gr >> 5) * 32 + s) * UU + n0 + tx * 4;
            float4 c = *reinterpret_cast<const float4*>(p);
            c.x += v.x; c.y += v.y; c.z += v.z; c.w += v.w;
            *reinterpret_cast<float4*>(p) = c;
        } else {  // MODE 2
            *reinterpret_cast<float4*>(C0 + (size_t)gr * UU + n0 + tx * 4) = v;
            if (gr >= 32) {
                float* p = out + (size_t)(gr & 31) * TU +
                           (size_t)((gr >> 5) * 32 + s) * UU + n0 + tx * 4;
                float4 c = *reinterpret_cast<const float4*>(p);
                c.x += v.x; c.y += v.y; c.z += v.z; c.w += v.w;
                *reinterpret_cast<float4*>(p) = c;
            }
        }
    }
}

// ---------------- phase 2: chunk carry  E_i = L_i + E_{i-1} @ R^32 ---------
// 128 blocks = 8 batch-groups x 16 u-groups; barrier per batch-group.
// carry row layout: row = chunk*32 + b. E_i stored at chunk (i+1) rows.
__global__ __launch_bounds__(256, 1) void carry_scan(float* __restrict__ out,
                                                     const float* __restrict__ R32,
                                                     float* __restrict__ carry) {
    const int bg   = blockIdx.x >> 4;
    const int ug   = blockIdx.x & 15;
    const int b0   = bg * 4;
    const int u0   = ug * 32;
    const int warp = threadIdx.x >> 5;
    const int lane = threadIdx.x & 31;
    const int uw   = u0 + warp * 4;
    const int slot = bg * 32;

    float Rreg[16][4];
    #pragma unroll
    for (int j = 0; j < 16; j++) {
        float4 v = *reinterpret_cast<const float4*>(
            R32 + (size_t)(lane + 32 * j) * UNITS + uw);
        Rreg[j][0] = v.x; Rreg[j][1] = v.y; Rreg[j][2] = v.z; Rreg[j][3] = v.w;
    }

    // seed E_0 = out[:,31,:] into carry chunk-1 rows
    if (threadIdx.x < 128) {
        const int b = threadIdx.x >> 5;
        const int u = u0 + (threadIdx.x & 31);
        carry[(size_t)(32 + b0 + b) * UNITS + u] =
            out[(size_t)(b0 + b) * TU + 31 * UNITS + u];
    }

    unsigned my_gen = ld_vol(&g_gen[slot]);

    for (int i = 1; i <= 31; i++) {
        // barrier among the 16 blocks of this batch-group (also orders seed)
        __threadfence();
        __syncthreads();
        if (threadIdx.x == 0) {
            __threadfence();
            if (atomicAdd(&g_cnt[slot], 1u) == 15u) {
                atomicExch(&g_cnt[slot], 0u);
                __threadfence();
                atomicAdd(&g_gen[slot], 1u);
            } else {
                while (ld_vol(&g_gen[slot]) == my_gen) { }
                __threadfence();
            }
        }
        __syncthreads();
        my_gen++;
        if (i == 31) break;  // E_31 not needed

        const float* h0p = carry + (size_t)(i * 32 + b0 + 0) * UNITS;
        const float* h1p = h0p + UNITS;
        const float* h2p = h1p + UNITS;
        const float* h3p = h2p + UNITS;

        float acc[16];
        #pragma unroll
        for (int q = 0; q < 16; q++) acc[q] = 0.f;

        #pragma unroll
        for (int j = 0; j < 16; j++) {
            const int k = lane + 32 * j;
            float h0 = __ldcg(h0p + k);
            float h1 = __ldcg(h1p + k);
            float h2 = __ldcg(h2p + k);
            float h3 = __ldcg(h3p + k);
            #pragma unroll
            for (int c = 0; c < 4; c++) {
                acc[0 + c]  += h0 * Rreg[j][c];
                acc[4 + c]  += h1 * Rreg[j][c];
                acc[8 + c]  += h2 * Rreg[j][c];
                acc[12 + c] += h3 * Rreg[j][c];
            }
        }
        #pragma unroll
        for (int q = 0; q < 16; q++) {
            #pragma unroll
            for (int off = 16; off >= 1; off >>= 1)
                acc[q] += __shfl_xor_sync(0xffffffffu, acc[q], off);
        }
        if (lane < 16) {
            float ssum = acc[0];
            #pragma unroll
            for (int q = 1; q < 16; q++) ssum = (lane == q) ? acc[q] : ssum;
            const int b = lane >> 2, c = lane & 3;
            const float Lval = __ldcg(out + (size_t)(b0 + b) * TU +
                                      (size_t)(i * 32 + 31) * UNITS + uw + c);
            __stcg(carry + (size_t)((i + 1) * 32 + b0 + b) * UNITS + uw + c,
                   Lval + ssum);
        }
    }
}

extern "C" void kernel_launch(void* const* d_in, const int* in_sizes, int n_in,
                              void* d_out, int out_size) {
    const float* x = (const float*)d_in[0];   // [32,1024,512]
    const float* W = (const float*)d_in[1];   // [512,512]
    const float* R = (const float*)d_in[2];   // [512,512]
    float* out = (float*)d_out;               // [32,1024,512]

    float *RpA, *RpB, *c0, *c1;
    cudaGetSymbolAddress((void**)&RpA, g_RpA);
    cudaGetSymbolAddress((void**)&RpB, g_RpB);
    cudaGetSymbolAddress((void**)&c0, g_carry0);
    cudaGetSymbolAddress((void**)&c1, g_carry1);

    // front GEMM: out = x @ W
    dim3 grid_gemm(UNITS / 128, (BATCH * TSTEPS) / 128);
    gemm_xw<<<grid_gemm, 256>>>(x, W, out);

    // R^32 by repeated squaring (independent of xw; same stream is fine)
    dim3 gpow(8, 8);
    gemm64<0><<<gpow, 256>>>(R,   R,   RpA, nullptr, 0);   // R^2
    gemm64<0><<<gpow, 256>>>(RpA, RpA, RpB, nullptr, 0);   // R^4
    gemm64<0><<<gpow, 256>>>(RpB, RpB, RpA, nullptr, 0);   // R^8
    gemm64<0><<<gpow, 256>>>(RpA, RpA, RpB, nullptr, 0);   // R^16
    gemm64<0><<<gpow, 256>>>(RpB, RpB, RpA, nullptr, 0);   // R^32 -> RpA

    // phase 1: local scans within each 32-step chunk
    dim3 g1(8, 16);
    for (int s = 1; s < 32; s++)
        gemm64<1><<<g1, 256>>>(nullptr, R, nullptr, out, s);

    // phase 2: sequential chunk carries with R^32
    carry_scan<<<128, 256>>>(out, RpA, c0);

    // phase 3: apply carries: carry <- carry @ R; out[:, chunk*32+s, :] += carry
    for (int s = 0; s < 32; s++) {
        float* cin  = (s & 1) ? c1 : c0;
        float* cout = (s & 1) ? c0 : c1;
        gemm64<2><<<g1, 256>>>(cin, R, cout, out, s);
    }
}